// round 3
// baseline (speedup 1.0000x reference)
#include <cuda_runtime.h>
#include <cuda_fp16.h>
#include <stdint.h>

// ---------------------------------------------------------------------------
// Problem constants
// ---------------------------------------------------------------------------
#define DIN        64
#define HID        256
#define ROWS_TOTAL (256 * 2048)            // 524288
#define WARP_M     16
#define WTILES     (ROWS_TOTAL / WARP_M)   // 32768
#define NTHREADS   256
#define GRID_SMS   148
#define NWARPS_TOT (GRID_SMS * (NTHREADS / 32))  // 1184
#define MIN_VAL    (-1e8f)

// ---------------------------------------------------------------------------
// SMEM layout (bytes). Padded strides: odd multiples of 16B -> conflict-free
// ldmatrix row addressing.
// ---------------------------------------------------------------------------
#define XSTRIDE_H  72          // halfs per row (144B = 9*16B)
#define W2STRIDE_H 264         // halfs per row (528B = 33*16B)

#define SM_X      0                               // 8 warps * 16*72*2 = 18432
#define SM_W1T    (SM_X + 8 * WARP_M * XSTRIDE_H * 2)      // 256*72*2 = 36864
#define SM_W2T    (SM_W1T + HID * XSTRIDE_H * 2)           // 256*264*2 = 135168
#define SM_S      (SM_W2T + HID * W2STRIDE_H * 2)          // 256 f32
#define SM_C      (SM_S + 1024)
#define SM_B2     (SM_C + 1024)
#define SM_W3     (SM_B2 + 1024)
#define SM_TOTAL  (SM_W3 + 1024)

// ---------------------------------------------------------------------------
// Helpers
// ---------------------------------------------------------------------------
__device__ __forceinline__ uint32_t smem_u32(const void* p) {
    uint32_t a;
    asm("{ .reg .u64 t; cvta.to.shared.u64 t, %1; cvt.u32.u64 %0, t; }" : "=r"(a) : "l"(p));
    return a;
}

__device__ __forceinline__ uint32_t h2u(__half2 v) {
    return *reinterpret_cast<uint32_t*>(&v);
}

__device__ __forceinline__ void ldm4(uint32_t* r, uint32_t addr) {
    asm volatile("ldmatrix.sync.aligned.m8n8.x4.shared.b16 {%0,%1,%2,%3}, [%4];"
                 : "=r"(r[0]), "=r"(r[1]), "=r"(r[2]), "=r"(r[3]) : "r"(addr));
}

__device__ __forceinline__ void mma16816(float* c,
                                         uint32_t a0, uint32_t a1, uint32_t a2, uint32_t a3,
                                         uint32_t b0, uint32_t b1) {
    asm volatile("mma.sync.aligned.m16n8k16.row.col.f32.f16.f16.f32 "
                 "{%0,%1,%2,%3}, {%4,%5,%6,%7}, {%8,%9}, {%0,%1,%2,%3};"
                 : "+f"(c[0]), "+f"(c[1]), "+f"(c[2]), "+f"(c[3])
                 : "r"(a0), "r"(a1), "r"(a2), "r"(a3), "r"(b0), "r"(b1));
}

// ---------------------------------------------------------------------------
// Kernel
// ---------------------------------------------------------------------------
__global__ void __launch_bounds__(NTHREADS, 1) node_mlp_kernel(
    const float* __restrict__ obs, const int* __restrict__ mask,
    const float* __restrict__ W1, const float* __restrict__ b1,
    const float* __restrict__ gamma, const float* __restrict__ beta,
    const float* __restrict__ rmean, const float* __restrict__ rvar,
    const float* __restrict__ W2, const float* __restrict__ b2,
    const float* __restrict__ W3, const float* __restrict__ b3,
    float* __restrict__ out)
{
    extern __shared__ char smem[];
    const uint32_t sb = smem_u32(smem);
    const int tid  = threadIdx.x;
    const int wid  = tid >> 5;
    const int lane = tid & 31;

    __half* w1t = (__half*)(smem + SM_W1T);
    __half* w2t = (__half*)(smem + SM_W2T);

    // ---- one-time weight staging ----
    for (int idx = tid; idx < DIN * HID; idx += NTHREADS) {
        int k = idx >> 8, n = idx & 255;           // W1[k][n]
        w1t[n * XSTRIDE_H + k] = __float2half(W1[idx]);
    }
    for (int idx = tid; idx < HID * HID; idx += NTHREADS) {
        int k = idx >> 8, n = idx & 255;           // W2[k][n]
        w2t[n * W2STRIDE_H + k] = __float2half(W2[idx]);
    }
    for (int n = tid; n < HID; n += NTHREADS) {
        float s = gamma[n] * rsqrtf(rvar[n] + 1e-5f);
        ((float*)(smem + SM_S))[n]  = s;
        ((float*)(smem + SM_C))[n]  = (b1[n] - rmean[n]) * s + beta[n];
        ((float*)(smem + SM_B2))[n] = b2[n];
        ((float*)(smem + SM_W3))[n] = W3[n];
    }
    const float b3v = __ldg(b3);
    __syncthreads();

    const float* Sv  = (const float*)(smem + SM_S);
    const float* Cv  = (const float*)(smem + SM_C);
    const float* B2v = (const float*)(smem + SM_B2);
    const float* W3v = (const float*)(smem + SM_W3);

    const uint32_t xbase = sb + SM_X + wid * (WARP_M * XSTRIDE_H * 2);
    // ldmatrix per-lane address components (16 rows, two 8-half column blocks)
    const uint32_t lrow = (uint32_t)(lane & 15);
    const uint32_t lcol = (uint32_t)(lane >> 4) * 16;       // bytes
    const uint32_t a_addr  = xbase + lrow * (XSTRIDE_H * 2) + lcol;
    const uint32_t w1_addr = sb + SM_W1T + lrow * (XSTRIDE_H * 2) + lcol;
    const uint32_t w2_addr = sb + SM_W2T + lrow * (W2STRIDE_H * 2) + lcol;

    const int g  = lane >> 2;           // 0..7 (output row within 8-row group)
    const int t2 = (lane & 3) * 2;      // 0,2,4,6 (output col pair)

    const int gwid = blockIdx.x * (NTHREADS / 32) + wid;

    for (int wt = gwid; wt < WTILES; wt += NWARPS_TOT) {
        const int row0 = wt * WARP_M;

        // ---- load X 16x64 f32 -> f16 into this warp's smem slab ----
        {
            const int r    = lane >> 1;          // 0..15
            const int hsel = lane & 1;           // half of the 64 cols
            const float4* src = (const float4*)(obs + (size_t)(row0 + r) * DIN + hsel * 32);
            uint32_t dst = xbase + (uint32_t)r * (XSTRIDE_H * 2) + (uint32_t)hsel * 64;
            #pragma unroll
            for (int i = 0; i < 8; i++) {
                float4 v = src[i];
                uint2 pk;
                pk.x = h2u(__floats2half2_rn(v.x, v.y));
                pk.y = h2u(__floats2half2_rn(v.z, v.w));
                *(uint2*)(smem + (dst - sb) + i * 8) = pk;
            }
        }
        __syncwarp();

        // ---- A fragments for GEMM1 (k = 4 steps of 16) ----
        uint32_t a[4][4];
        #pragma unroll
        for (int kk = 0; kk < 4; kk++) ldm4(a[kk], a_addr + kk * 32);

        // ---- GEMM1 (16x256x64) + BN + ReLU -> h1 in registers (f16x2) ----
        uint32_t h1lo[32], h1hi[32];   // per n-tile j: rows g / g+8, cols 8j+t2,+1
        #pragma unroll
        for (int cc = 0; cc < 4; cc++) {
            float c[8][4];
            #pragma unroll
            for (int j = 0; j < 8; j++) { c[j][0]=0.f; c[j][1]=0.f; c[j][2]=0.f; c[j][3]=0.f; }
            #pragma unroll
            for (int kk = 0; kk < 4; kk++) {
                #pragma unroll
                for (int p = 0; p < 4; p++) {
                    uint32_t b[4];
                    ldm4(b, w1_addr + (uint32_t)(cc * 64 + 16 * p) * (XSTRIDE_H * 2) + kk * 32);
                    mma16816(c[2*p],   a[kk][0], a[kk][1], a[kk][2], a[kk][3], b[0], b[2]);
                    mma16816(c[2*p+1], a[kk][0], a[kk][1], a[kk][2], a[kk][3], b[1], b[3]);
                }
            }
            #pragma unroll
            for (int j = 0; j < 8; j++) {
                int n = cc * 64 + 8 * j + t2;
                float s0 = Sv[n], s1 = Sv[n+1], d0 = Cv[n], d1 = Cv[n+1];
                float v00 = fmaxf(fmaf(c[j][0], s0, d0), 0.0f);
                float v01 = fmaxf(fmaf(c[j][1], s1, d1), 0.0f);
                float v10 = fmaxf(fmaf(c[j][2], s0, d0), 0.0f);
                float v11 = fmaxf(fmaf(c[j][3], s1, d1), 0.0f);
                h1lo[cc*8 + j] = h2u(__floats2half2_rn(v00, v01));
                h1hi[cc*8 + j] = h2u(__floats2half2_rn(v10, v11));
            }
        }

        // ---- GEMM2 (16x256x256, A from registers) + bias + ReLU + dot(W3) ----
        float yg = 0.0f, yh = 0.0f;
        for (int cc = 0; cc < 4; cc++) {            // not unrolled (code size)
            float c[8][4];
            #pragma unroll
            for (int j = 0; j < 8; j++) { c[j][0]=0.f; c[j][1]=0.f; c[j][2]=0.f; c[j][3]=0.f; }
            uint32_t wbase = w2_addr + (uint32_t)(cc * 64) * (W2STRIDE_H * 2);
            #pragma unroll
            for (int kk = 0; kk < 16; kk++) {
                uint32_t a0 = h1lo[2*kk], a1 = h1hi[2*kk];
                uint32_t a2 = h1lo[2*kk+1], a3 = h1hi[2*kk+1];
                #pragma unroll
                for (int p = 0; p < 4; p++) {
                    uint32_t b[4];
                    ldm4(b, wbase + (uint32_t)(16 * p) * (W2STRIDE_H * 2) + kk * 32);
                    mma16816(c[2*p],   a0, a1, a2, a3, b[0], b[2]);
                    mma16816(c[2*p+1], a0, a1, a2, a3, b[1], b[3]);
                }
            }
            #pragma unroll
            for (int j = 0; j < 8; j++) {
                int n = cc * 64 + 8 * j + t2;
                float bb0 = B2v[n], bb1 = B2v[n+1], w30 = W3v[n], w31 = W3v[n+1];
                yg = fmaf(fmaxf(c[j][0] + bb0, 0.0f), w30, yg);
                yg = fmaf(fmaxf(c[j][1] + bb1, 0.0f), w31, yg);
                yh = fmaf(fmaxf(c[j][2] + bb0, 0.0f), w30, yh);
                yh = fmaf(fmaxf(c[j][3] + bb1, 0.0f), w31, yh);
            }
        }

        // ---- reduce over the 4 lanes of each row group, store ----
        yg += __shfl_xor_sync(0xFFFFFFFF, yg, 1);
        yg += __shfl_xor_sync(0xFFFFFFFF, yg, 2);
        yh += __shfl_xor_sync(0xFFFFFFFF, yh, 1);
        yh += __shfl_xor_sync(0xFFFFFFFF, yh, 2);
        if ((lane & 3) == 0) {
            int r1 = row0 + g;
            int r2 = row0 + 8 + g;
            out[r1] = (mask[r1] != 0) ? (yg + b3v) : MIN_VAL;
            out[r2] = (mask[r2] != 0) ? (yh + b3v) : MIN_VAL;
        }
        __syncwarp();
    }
}

// ---------------------------------------------------------------------------
// Launch
// ---------------------------------------------------------------------------
extern "C" void kernel_launch(void* const* d_in, const int* in_sizes, int n_in,
                              void* d_out, int out_size)
{
    (void)in_sizes; (void)n_in; (void)out_size;
    cudaFuncSetAttribute(node_mlp_kernel,
                         cudaFuncAttributeMaxDynamicSharedMemorySize, SM_TOTAL);
    node_mlp_kernel<<<GRID_SMS, NTHREADS, SM_TOTAL>>>(
        (const float*)d_in[0],  // obs
        (const int*)d_in[1],    // mask
        (const float*)d_in[2],  // W1
        (const float*)d_in[3],  // b1
        (const float*)d_in[4],  // gamma
        (const float*)d_in[5],  // beta
        (const float*)d_in[6],  // run_mean
        (const float*)d_in[7],  // run_var
        (const float*)d_in[8],  // W2
        (const float*)d_in[9],  // b2
        (const float*)d_in[10], // W3
        (const float*)d_in[11], // b3
        (float*)d_out);
}

// round 4
// speedup vs baseline: 1.7985x; 1.7985x over previous
#include <cuda_runtime.h>
#include <cuda_fp16.h>
#include <stdint.h>

// ---------------------------------------------------------------------------
// Problem constants
// ---------------------------------------------------------------------------
#define DIN        64
#define HID        256
#define ROWS_TOTAL (256 * 2048)            // 524288
#define WARP_M     16
#define NTHREADS   256
#define GRID_SMS   148
#define NWARPS_TOT (GRID_SMS * (NTHREADS / 32))  // 1184
#define MIN_VAL    (-1e8f)

// ---------------------------------------------------------------------------
// Device globals: compaction state (static allocation — allowed)
// ---------------------------------------------------------------------------
__device__ int g_count;
__device__ int g_idx[ROWS_TOTAL];

// ---------------------------------------------------------------------------
// SMEM layout (bytes). Padded strides: odd multiples of 16B -> conflict-free
// ldmatrix row addressing.
// ---------------------------------------------------------------------------
#define XSTRIDE_H  72          // halfs per row (144B = 9*16B)
#define W2STRIDE_H 264         // halfs per row (528B = 33*16B)

#define SM_X      0                               // 8 warps * 16*72*2 = 18432
#define SM_W1T    (SM_X + 8 * WARP_M * XSTRIDE_H * 2)      // 256*72*2 = 36864
#define SM_W2T    (SM_W1T + HID * XSTRIDE_H * 2)           // 256*264*2 = 135168
#define SM_S      (SM_W2T + HID * W2STRIDE_H * 2)          // 256 f32
#define SM_C      (SM_S + 1024)
#define SM_B2     (SM_C + 1024)
#define SM_W3     (SM_B2 + 1024)
#define SM_TOTAL  (SM_W3 + 1024)

// ---------------------------------------------------------------------------
// Helpers
// ---------------------------------------------------------------------------
__device__ __forceinline__ uint32_t smem_u32(const void* p) {
    uint32_t a;
    asm("{ .reg .u64 t; cvta.to.shared.u64 t, %1; cvt.u32.u64 %0, t; }" : "=r"(a) : "l"(p));
    return a;
}

__device__ __forceinline__ uint32_t h2u(__half2 v) {
    return *reinterpret_cast<uint32_t*>(&v);
}

__device__ __forceinline__ void ldm4(uint32_t* r, uint32_t addr) {
    asm volatile("ldmatrix.sync.aligned.m8n8.x4.shared.b16 {%0,%1,%2,%3}, [%4];"
                 : "=r"(r[0]), "=r"(r[1]), "=r"(r[2]), "=r"(r[3]) : "r"(addr));
}

__device__ __forceinline__ void mma16816(float* c,
                                         uint32_t a0, uint32_t a1, uint32_t a2, uint32_t a3,
                                         uint32_t b0, uint32_t b1) {
    asm volatile("mma.sync.aligned.m16n8k16.row.col.f32.f16.f16.f32 "
                 "{%0,%1,%2,%3}, {%4,%5,%6,%7}, {%8,%9}, {%0,%1,%2,%3};"
                 : "+f"(c[0]), "+f"(c[1]), "+f"(c[2]), "+f"(c[3])
                 : "r"(a0), "r"(a1), "r"(a2), "r"(a3), "r"(b0), "r"(b1));
}

// ---------------------------------------------------------------------------
// Kernel 0: zero the compaction counter
// ---------------------------------------------------------------------------
__global__ void zero_kernel() {
    g_count = 0;
}

// ---------------------------------------------------------------------------
// Kernel 1: init output to MIN_VAL, build compacted valid-row index list
// ---------------------------------------------------------------------------
__global__ void prep_kernel(const int* __restrict__ mask, float* __restrict__ out) {
    int row = blockIdx.x * blockDim.x + threadIdx.x;
    if (row < ROWS_TOTAL) {
        out[row] = MIN_VAL;
        if (mask[row] != 0) {
            int p = atomicAdd(&g_count, 1);
            g_idx[p] = row;
        }
    }
}

// ---------------------------------------------------------------------------
// Main kernel
// ---------------------------------------------------------------------------
__global__ void __launch_bounds__(NTHREADS, 1) node_mlp_kernel(
    const float* __restrict__ obs,
    const float* __restrict__ W1, const float* __restrict__ b1,
    const float* __restrict__ gamma, const float* __restrict__ beta,
    const float* __restrict__ rmean, const float* __restrict__ rvar,
    const float* __restrict__ W2, const float* __restrict__ b2,
    const float* __restrict__ W3, const float* __restrict__ b3,
    float* __restrict__ out)
{
    extern __shared__ char smem[];
    const uint32_t sb = smem_u32(smem);
    const int tid  = threadIdx.x;
    const int wid  = tid >> 5;
    const int lane = tid & 31;

    __half* w1t = (__half*)(smem + SM_W1T);
    __half* w2t = (__half*)(smem + SM_W2T);

    // ---- one-time weight staging ----
    for (int idx = tid; idx < DIN * HID; idx += NTHREADS) {
        int k = idx >> 8, n = idx & 255;           // W1[k][n]
        w1t[n * XSTRIDE_H + k] = __float2half(W1[idx]);
    }
    for (int idx = tid; idx < HID * HID; idx += NTHREADS) {
        int k = idx >> 8, n = idx & 255;           // W2[k][n]
        w2t[n * W2STRIDE_H + k] = __float2half(W2[idx]);
    }
    for (int n = tid; n < HID; n += NTHREADS) {
        float s = gamma[n] * rsqrtf(rvar[n] + 1e-5f);
        ((float*)(smem + SM_S))[n]  = s;
        ((float*)(smem + SM_C))[n]  = (b1[n] - rmean[n]) * s + beta[n];
        ((float*)(smem + SM_B2))[n] = b2[n];
        ((float*)(smem + SM_W3))[n] = W3[n];
    }
    const float b3v = __ldg(b3);
    __syncthreads();

    const float* Sv  = (const float*)(smem + SM_S);
    const float* Cv  = (const float*)(smem + SM_C);
    const float* B2v = (const float*)(smem + SM_B2);
    const float* W3v = (const float*)(smem + SM_W3);

    const int cnt    = g_count;                    // valid rows
    const int ntiles = (cnt + WARP_M - 1) >> 4;    // 16-row warp tiles

    const uint32_t xbase = sb + SM_X + wid * (WARP_M * XSTRIDE_H * 2);
    const uint32_t lrow = (uint32_t)(lane & 15);
    const uint32_t lcol = (uint32_t)(lane >> 4) * 16;       // bytes
    const uint32_t a_addr  = xbase + lrow * (XSTRIDE_H * 2) + lcol;
    const uint32_t w1_addr = sb + SM_W1T + lrow * (XSTRIDE_H * 2) + lcol;
    const uint32_t w2_addr = sb + SM_W2T + lrow * (W2STRIDE_H * 2) + lcol;

    const int g  = lane >> 2;           // 0..7 (output row within 8-row group)
    const int t2 = (lane & 3) * 2;      // 0,2,4,6 (output col pair)

    const int gwid = blockIdx.x * (NTHREADS / 32) + wid;

    for (int wt = gwid; wt < ntiles; wt += NWARPS_TOT) {
        const int i0 = wt * WARP_M;     // index into compacted list

        // ---- gather X 16x64 f32 -> f16 into this warp's smem slab ----
        {
            const int r    = lane >> 1;          // 0..15
            const int hsel = lane & 1;
            const int gi   = min(i0 + r, cnt - 1);
            const int row  = g_idx[gi];
            const float4* src = (const float4*)(obs + (size_t)row * DIN + hsel * 32);
            uint32_t dst = xbase + (uint32_t)r * (XSTRIDE_H * 2) + (uint32_t)hsel * 64;
            #pragma unroll
            for (int i = 0; i < 8; i++) {
                float4 v = src[i];
                uint2 pk;
                pk.x = h2u(__floats2half2_rn(v.x, v.y));
                pk.y = h2u(__floats2half2_rn(v.z, v.w));
                *(uint2*)(smem + (dst - sb) + i * 8) = pk;
            }
        }
        __syncwarp();

        // ---- A fragments for GEMM1 (k = 4 steps of 16) ----
        uint32_t a[4][4];
        #pragma unroll
        for (int kk = 0; kk < 4; kk++) ldm4(a[kk], a_addr + kk * 32);

        // ---- GEMM1 (16x256x64) + BN + ReLU -> h1 in registers (f16x2) ----
        uint32_t h1lo[32], h1hi[32];
        #pragma unroll
        for (int cc = 0; cc < 4; cc++) {
            float c[8][4];
            #pragma unroll
            for (int j = 0; j < 8; j++) { c[j][0]=0.f; c[j][1]=0.f; c[j][2]=0.f; c[j][3]=0.f; }
            #pragma unroll
            for (int kk = 0; kk < 4; kk++) {
                #pragma unroll
                for (int p = 0; p < 4; p++) {
                    uint32_t b[4];
                    ldm4(b, w1_addr + (uint32_t)(cc * 64 + 16 * p) * (XSTRIDE_H * 2) + kk * 32);
                    mma16816(c[2*p],   a[kk][0], a[kk][1], a[kk][2], a[kk][3], b[0], b[2]);
                    mma16816(c[2*p+1], a[kk][0], a[kk][1], a[kk][2], a[kk][3], b[1], b[3]);
                }
            }
            #pragma unroll
            for (int j = 0; j < 8; j++) {
                int n = cc * 64 + 8 * j + t2;
                float s0 = Sv[n], s1 = Sv[n+1], d0 = Cv[n], d1 = Cv[n+1];
                float v00 = fmaxf(fmaf(c[j][0], s0, d0), 0.0f);
                float v01 = fmaxf(fmaf(c[j][1], s1, d1), 0.0f);
                float v10 = fmaxf(fmaf(c[j][2], s0, d0), 0.0f);
                float v11 = fmaxf(fmaf(c[j][3], s1, d1), 0.0f);
                h1lo[cc*8 + j] = h2u(__floats2half2_rn(v00, v01));
                h1hi[cc*8 + j] = h2u(__floats2half2_rn(v10, v11));
            }
        }

        // ---- GEMM2 (16x256x256, A from registers) + bias + ReLU + dot(W3) ----
        float yg = 0.0f, yh = 0.0f;
        for (int cc = 0; cc < 4; cc++) {
            float c[8][4];
            #pragma unroll
            for (int j = 0; j < 8; j++) { c[j][0]=0.f; c[j][1]=0.f; c[j][2]=0.f; c[j][3]=0.f; }
            uint32_t wbase = w2_addr + (uint32_t)(cc * 64) * (W2STRIDE_H * 2);
            #pragma unroll
            for (int kk = 0; kk < 16; kk++) {
                uint32_t a0 = h1lo[2*kk], a1 = h1hi[2*kk];
                uint32_t a2 = h1lo[2*kk+1], a3 = h1hi[2*kk+1];
                #pragma unroll
                for (int p = 0; p < 4; p++) {
                    uint32_t b[4];
                    ldm4(b, wbase + (uint32_t)(16 * p) * (W2STRIDE_H * 2) + kk * 32);
                    mma16816(c[2*p],   a0, a1, a2, a3, b[0], b[2]);
                    mma16816(c[2*p+1], a0, a1, a2, a3, b[1], b[3]);
                }
            }
            #pragma unroll
            for (int j = 0; j < 8; j++) {
                int n = cc * 64 + 8 * j + t2;
                float bb0 = B2v[n], bb1 = B2v[n+1], w30 = W3v[n], w31 = W3v[n+1];
                yg = fmaf(fmaxf(c[j][0] + bb0, 0.0f), w30, yg);
                yg = fmaf(fmaxf(c[j][1] + bb1, 0.0f), w31, yg);
                yh = fmaf(fmaxf(c[j][2] + bb0, 0.0f), w30, yh);
                yh = fmaf(fmaxf(c[j][3] + bb1, 0.0f), w31, yh);
            }
        }

        // ---- reduce over the 4 lanes of each row group, scatter ----
        yg += __shfl_xor_sync(0xFFFFFFFF, yg, 1);
        yg += __shfl_xor_sync(0xFFFFFFFF, yg, 2);
        yh += __shfl_xor_sync(0xFFFFFFFF, yh, 1);
        yh += __shfl_xor_sync(0xFFFFFFFF, yh, 2);
        if ((lane & 3) == 0) {
            int i1 = i0 + g;
            int i2 = i0 + 8 + g;
            if (i1 < cnt) out[g_idx[i1]] = yg + b3v;
            if (i2 < cnt) out[g_idx[i2]] = yh + b3v;
        }
        __syncwarp();
    }
}

// ---------------------------------------------------------------------------
// Launch
// ---------------------------------------------------------------------------
extern "C" void kernel_launch(void* const* d_in, const int* in_sizes, int n_in,
                              void* d_out, int out_size)
{
    (void)in_sizes; (void)n_in; (void)out_size;
    cudaFuncSetAttribute(node_mlp_kernel,
                         cudaFuncAttributeMaxDynamicSharedMemorySize, SM_TOTAL);

    zero_kernel<<<1, 1>>>();
    prep_kernel<<<ROWS_TOTAL / 256, 256>>>((const int*)d_in[1], (float*)d_out);
    node_mlp_kernel<<<GRID_SMS, NTHREADS, SM_TOTAL>>>(
        (const float*)d_in[0],  // obs
        (const float*)d_in[2],  // W1
        (const float*)d_in[3],  // b1
        (const float*)d_in[4],  // gamma
        (const float*)d_in[5],  // beta
        (const float*)d_in[6],  // run_mean
        (const float*)d_in[7],  // run_var
        (const float*)d_in[8],  // W2
        (const float*)d_in[9],  // b2
        (const float*)d_in[10], // W3
        (const float*)d_in[11], // b3
        (float*)d_out);
}

// round 5
// speedup vs baseline: 1.8269x; 1.0158x over previous
#include <cuda_runtime.h>
#include <cuda_fp16.h>
#include <stdint.h>

// ---------------------------------------------------------------------------
// Problem constants
// ---------------------------------------------------------------------------
#define DIN        64
#define HID        256
#define ROWS_TOTAL (256 * 2048)            // 524288
#define WARP_M     32
#define NTHREADS   256
#define GRID_SMS   148
#define NWARPS_TOT (GRID_SMS * (NTHREADS / 32))  // 1184
#define MIN_VAL    (-1e8f)

// ---------------------------------------------------------------------------
// Device globals: compaction state
// ---------------------------------------------------------------------------
__device__ int g_count;
__device__ int g_idx[ROWS_TOTAL];

// ---------------------------------------------------------------------------
// SMEM layout (bytes). Padded strides: odd multiples of 16B -> conflict-free
// ldmatrix row addressing.
// ---------------------------------------------------------------------------
#define XSTRIDE_H  72          // halfs per row (144B = 9*16B)
#define W2STRIDE_H 264         // halfs per row (528B = 33*16B)

#define SM_X      0                                        // 8 * 32*72*2 = 36864
#define SM_W1T    (SM_X + 8 * WARP_M * XSTRIDE_H * 2)      // 256*72*2 = 36864
#define SM_W2T    (SM_W1T + HID * XSTRIDE_H * 2)           // 256*264*2 = 135168
#define SM_S      (SM_W2T + HID * W2STRIDE_H * 2)
#define SM_C      (SM_S + 1024)
#define SM_B2     (SM_C + 1024)
#define SM_W3     (SM_B2 + 1024)
#define SM_TOTAL  (SM_W3 + 1024)                           // 212992

// ---------------------------------------------------------------------------
// Helpers
// ---------------------------------------------------------------------------
__device__ __forceinline__ uint32_t smem_u32(const void* p) {
    uint32_t a;
    asm("{ .reg .u64 t; cvta.to.shared.u64 t, %1; cvt.u32.u64 %0, t; }" : "=r"(a) : "l"(p));
    return a;
}

__device__ __forceinline__ uint32_t h2u(__half2 v) {
    return *reinterpret_cast<uint32_t*>(&v);
}

__device__ __forceinline__ void ldm4(uint32_t* r, uint32_t addr) {
    asm volatile("ldmatrix.sync.aligned.m8n8.x4.shared.b16 {%0,%1,%2,%3}, [%4];"
                 : "=r"(r[0]), "=r"(r[1]), "=r"(r[2]), "=r"(r[3]) : "r"(addr));
}

__device__ __forceinline__ void mma16816(float* c,
                                         uint32_t a0, uint32_t a1, uint32_t a2, uint32_t a3,
                                         uint32_t b0, uint32_t b1) {
    asm volatile("mma.sync.aligned.m16n8k16.row.col.f32.f16.f16.f32 "
                 "{%0,%1,%2,%3}, {%4,%5,%6,%7}, {%8,%9}, {%0,%1,%2,%3};"
                 : "+f"(c[0]), "+f"(c[1]), "+f"(c[2]), "+f"(c[3])
                 : "r"(a0), "r"(a1), "r"(a2), "r"(a3), "r"(b0), "r"(b1));
}

// ---------------------------------------------------------------------------
// Kernel 0: zero the compaction counter
// ---------------------------------------------------------------------------
__global__ void zero_kernel() {
    g_count = 0;
}

// ---------------------------------------------------------------------------
// Kernel 1: init output to MIN_VAL, build compacted valid-row index list
// ---------------------------------------------------------------------------
__global__ void prep_kernel(const int* __restrict__ mask, float* __restrict__ out) {
    int row = blockIdx.x * blockDim.x + threadIdx.x;
    if (row < ROWS_TOTAL) {
        out[row] = MIN_VAL;
        if (mask[row] != 0) {
            int p = atomicAdd(&g_count, 1);
            g_idx[p] = row;
        }
    }
}

// ---------------------------------------------------------------------------
// Main kernel: 32 rows per warp, fully warp-private inner loop
// ---------------------------------------------------------------------------
__global__ void __launch_bounds__(NTHREADS, 1) node_mlp_kernel(
    const float* __restrict__ obs,
    const float* __restrict__ W1, const float* __restrict__ b1,
    const float* __restrict__ gamma, const float* __restrict__ beta,
    const float* __restrict__ rmean, const float* __restrict__ rvar,
    const float* __restrict__ W2, const float* __restrict__ b2,
    const float* __restrict__ W3, const float* __restrict__ b3,
    float* __restrict__ out)
{
    extern __shared__ char smem[];
    const uint32_t sb = smem_u32(smem);
    const int tid  = threadIdx.x;
    const int wid  = tid >> 5;
    const int lane = tid & 31;

    __half* w1t = (__half*)(smem + SM_W1T);
    __half* w2t = (__half*)(smem + SM_W2T);

    // ---- one-time weight staging ----
    for (int idx = tid; idx < DIN * HID; idx += NTHREADS) {
        int k = idx >> 8, n = idx & 255;           // W1[k][n]
        w1t[n * XSTRIDE_H + k] = __float2half(W1[idx]);
    }
    for (int idx = tid; idx < HID * HID; idx += NTHREADS) {
        int k = idx >> 8, n = idx & 255;           // W2[k][n]
        w2t[n * W2STRIDE_H + k] = __float2half(W2[idx]);
    }
    for (int n = tid; n < HID; n += NTHREADS) {
        float s = gamma[n] * rsqrtf(rvar[n] + 1e-5f);
        ((float*)(smem + SM_S))[n]  = s;
        ((float*)(smem + SM_C))[n]  = (b1[n] - rmean[n]) * s + beta[n];
        ((float*)(smem + SM_B2))[n] = b2[n];
        ((float*)(smem + SM_W3))[n] = W3[n];
    }
    const float b3v = __ldg(b3);
    __syncthreads();

    const float* Sv  = (const float*)(smem + SM_S);
    const float* Cv  = (const float*)(smem + SM_C);
    const float* B2v = (const float*)(smem + SM_B2);
    const float* W3v = (const float*)(smem + SM_W3);

    const int cnt    = g_count;
    const int ntiles = (cnt + WARP_M - 1) >> 5;    // 32-row warp tiles

    const uint32_t xbase = sb + SM_X + wid * (WARP_M * XSTRIDE_H * 2);
    const uint32_t lrow = (uint32_t)(lane & 15);
    const uint32_t lcol = (uint32_t)(lane >> 4) * 16;       // bytes
    const uint32_t a_addr  = xbase + lrow * (XSTRIDE_H * 2) + lcol;
    const uint32_t w1_addr = sb + SM_W1T + lrow * (XSTRIDE_H * 2) + lcol;
    const uint32_t w2_addr = sb + SM_W2T + lrow * (W2STRIDE_H * 2) + lcol;

    const int g  = lane >> 2;           // 0..7 (output row within 8-row group)
    const int t2 = (lane & 3) * 2;      // 0,2,4,6 (output col pair)

    const int gwid = blockIdx.x * (NTHREADS / 32) + wid;

    for (int wt = gwid; wt < ntiles; wt += NWARPS_TOT) {
        const int i0 = wt * WARP_M;     // index into compacted list

        // ---- gather X 32x64 f32 -> f16 into this warp's smem slab ----
        #pragma unroll
        for (int rr = 0; rr < 2; rr++) {
            const int r    = rr * 16 + (lane >> 1);
            const int hsel = lane & 1;
            const int gi   = min(i0 + r, cnt - 1);
            const int row  = g_idx[gi];
            const float4* src = (const float4*)(obs + (size_t)row * DIN + hsel * 32);
            uint32_t dstoff = (xbase - sb) + (uint32_t)r * (XSTRIDE_H * 2) + (uint32_t)hsel * 64;
            #pragma unroll
            for (int i = 0; i < 8; i++) {
                float4 v = src[i];
                uint2 pk;
                pk.x = h2u(__floats2half2_rn(v.x, v.y));
                pk.y = h2u(__floats2half2_rn(v.z, v.w));
                *(uint2*)(smem + dstoff + i * 8) = pk;
            }
        }
        __syncwarp();

        // ---- A fragments for GEMM1 (2 row blocks x 4 k-steps) ----
        uint32_t a[2][4][4];
        #pragma unroll
        for (int bb = 0; bb < 2; bb++)
            #pragma unroll
            for (int kk = 0; kk < 4; kk++)
                ldm4(a[bb][kk], a_addr + (uint32_t)bb * 16 * (XSTRIDE_H * 2) + kk * 32);

        // ---- GEMM1 (32x256x64) + BN + ReLU -> h1 in registers ----
        // h1[bb][2t] = lo(ntile t), h1[bb][2t+1] = hi(ntile t), t = 0..31
        uint32_t h1[2][64];
        #pragma unroll
        for (int cc = 0; cc < 4; cc++) {
            float c[2][8][4];
            #pragma unroll
            for (int bb = 0; bb < 2; bb++)
                #pragma unroll
                for (int j = 0; j < 8; j++)
                    { c[bb][j][0]=0.f; c[bb][j][1]=0.f; c[bb][j][2]=0.f; c[bb][j][3]=0.f; }
            #pragma unroll
            for (int kk = 0; kk < 4; kk++) {
                #pragma unroll
                for (int p = 0; p < 4; p++) {
                    uint32_t b[4];
                    ldm4(b, w1_addr + (uint32_t)(cc * 64 + 16 * p) * (XSTRIDE_H * 2) + kk * 32);
                    #pragma unroll
                    for (int bb = 0; bb < 2; bb++) {
                        mma16816(c[bb][2*p],   a[bb][kk][0], a[bb][kk][1], a[bb][kk][2], a[bb][kk][3], b[0], b[2]);
                        mma16816(c[bb][2*p+1], a[bb][kk][0], a[bb][kk][1], a[bb][kk][2], a[bb][kk][3], b[1], b[3]);
                    }
                }
            }
            #pragma unroll
            for (int bb = 0; bb < 2; bb++) {
                #pragma unroll
                for (int j = 0; j < 8; j++) {
                    int n = cc * 64 + 8 * j + t2;
                    int t = cc * 8 + j;
                    float s0 = Sv[n], s1 = Sv[n+1], d0 = Cv[n], d1 = Cv[n+1];
                    float v00 = fmaxf(fmaf(c[bb][j][0], s0, d0), 0.0f);
                    float v01 = fmaxf(fmaf(c[bb][j][1], s1, d1), 0.0f);
                    float v10 = fmaxf(fmaf(c[bb][j][2], s0, d0), 0.0f);
                    float v11 = fmaxf(fmaf(c[bb][j][3], s1, d1), 0.0f);
                    h1[bb][2*t]   = h2u(__floats2half2_rn(v00, v01));
                    h1[bb][2*t+1] = h2u(__floats2half2_rn(v10, v11));
                }
            }
        }

        // ---- GEMM2 (32x256x256, A from registers) + bias + ReLU + dot(W3) ----
        float y[2][2] = {{0.f, 0.f}, {0.f, 0.f}};
        for (int cc = 0; cc < 4; cc++) {            // not unrolled (code size)
            float c[2][8][4];
            #pragma unroll
            for (int bb = 0; bb < 2; bb++)
                #pragma unroll
                for (int j = 0; j < 8; j++)
                    { c[bb][j][0]=0.f; c[bb][j][1]=0.f; c[bb][j][2]=0.f; c[bb][j][3]=0.f; }
            uint32_t wbase = w2_addr + (uint32_t)(cc * 64) * (W2STRIDE_H * 2);
            #pragma unroll
            for (int kk = 0; kk < 16; kk++) {
                #pragma unroll
                for (int p = 0; p < 4; p++) {
                    uint32_t b[4];
                    ldm4(b, wbase + (uint32_t)(16 * p) * (W2STRIDE_H * 2) + kk * 32);
                    #pragma unroll
                    for (int bb = 0; bb < 2; bb++) {
                        mma16816(c[bb][2*p],   h1[bb][4*kk], h1[bb][4*kk+1], h1[bb][4*kk+2], h1[bb][4*kk+3], b[0], b[2]);
                        mma16816(c[bb][2*p+1], h1[bb][4*kk], h1[bb][4*kk+1], h1[bb][4*kk+2], h1[bb][4*kk+3], b[1], b[3]);
                    }
                }
            }
            #pragma unroll
            for (int bb = 0; bb < 2; bb++) {
                #pragma unroll
                for (int j = 0; j < 8; j++) {
                    int n = cc * 64 + 8 * j + t2;
                    float bb0 = B2v[n], bb1 = B2v[n+1], w30 = W3v[n], w31 = W3v[n+1];
                    y[bb][0] = fmaf(fmaxf(c[bb][j][0] + bb0, 0.0f), w30, y[bb][0]);
                    y[bb][0] = fmaf(fmaxf(c[bb][j][1] + bb1, 0.0f), w31, y[bb][0]);
                    y[bb][1] = fmaf(fmaxf(c[bb][j][2] + bb0, 0.0f), w30, y[bb][1]);
                    y[bb][1] = fmaf(fmaxf(c[bb][j][3] + bb1, 0.0f), w31, y[bb][1]);
                }
            }
        }

        // ---- reduce over 4 lanes per row group, scatter 4 rows ----
        #pragma unroll
        for (int bb = 0; bb < 2; bb++) {
            y[bb][0] += __shfl_xor_sync(0xFFFFFFFF, y[bb][0], 1);
            y[bb][0] += __shfl_xor_sync(0xFFFFFFFF, y[bb][0], 2);
            y[bb][1] += __shfl_xor_sync(0xFFFFFFFF, y[bb][1], 1);
            y[bb][1] += __shfl_xor_sync(0xFFFFFFFF, y[bb][1], 2);
        }
        if ((lane & 3) == 0) {
            #pragma unroll
            for (int bb = 0; bb < 2; bb++) {
                int i1 = i0 + bb * 16 + g;
                int i2 = i0 + bb * 16 + 8 + g;
                if (i1 < cnt) out[g_idx[i1]] = y[bb][0] + b3v;
                if (i2 < cnt) out[g_idx[i2]] = y[bb][1] + b3v;
            }
        }
        __syncwarp();
    }
}

// ---------------------------------------------------------------------------
// Launch
// ---------------------------------------------------------------------------
extern "C" void kernel_launch(void* const* d_in, const int* in_sizes, int n_in,
                              void* d_out, int out_size)
{
    (void)in_sizes; (void)n_in; (void)out_size;
    cudaFuncSetAttribute(node_mlp_kernel,
                         cudaFuncAttributeMaxDynamicSharedMemorySize, SM_TOTAL);

    zero_kernel<<<1, 1>>>();
    prep_kernel<<<ROWS_TOTAL / 256, 256>>>((const int*)d_in[1], (float*)d_out);
    node_mlp_kernel<<<GRID_SMS, NTHREADS, SM_TOTAL>>>(
        (const float*)d_in[0],  // obs
        (const float*)d_in[2],  // W1
        (const float*)d_in[3],  // b1
        (const float*)d_in[4],  // gamma
        (const float*)d_in[5],  // beta
        (const float*)d_in[6],  // run_mean
        (const float*)d_in[7],  // run_var
        (const float*)d_in[8],  // W2
        (const float*)d_in[9],  // b2
        (const float*)d_in[10], // W3
        (const float*)d_in[11], // b3
        (float*)d_out);
}